// round 8
// baseline (speedup 1.0000x reference)
#include <cuda_runtime.h>

#define NB 8
#define NC 3
#define NH 512
#define NW 512
#define HP 514
#define WP 514
#define BX 32
#define BY 16
#define NTX 32
#define NTY 24
#define NT (NTX * NTY)        // 768 threads

// shared tile dims
#define TX (BX + 6)           // 38  img_p cols (radius 3)
#define TY (BY + 6)           // 22  img_p rows
#define RX (BX + 4)           // 36  img_r cols (radius 2)
#define RY (BY + 4)           // 20
#define MX (BX + 2)           // 34  mod cols (radius 1)
#define MY (BY + 2)           // 18

struct Smem {
    float sp[NC][TY][TX];     // img_p tile
    float sr[RY][RX];         // img_r (zero outside image)
    float sm[MY][MX];         // img_3d_mod (zero outside image)
};

// raw 2^x (MUFU.EX2). exp(-z) == ex2(-z*log2e); log2e folded into 'a'.
static __device__ __forceinline__ float ex2f(float x)
{
    float r; asm("ex2.approx.f32 %0, %1;" : "=f"(r) : "f"(x)); return r;
}

template<bool IN>
static __device__ __forceinline__ void run_tile(
    Smem& S, int b, int by, int bx, int tid, int tx, int ty, int mix,
    const float* __restrict__ img, const float* __restrict__ noise,
    const float* __restrict__ re, float* __restrict__ out)
{
    // ---- load img_p tile: sp[c][ly][lx] = img_p[by-2+ly][bx-2+lx] ----
    for (int i = tid; i < NC * TY * TX; i += NT) {
        int c  = i / (TY * TX);
        int rm = i - c * (TY * TX);
        int ly = rm / TX, lx = rm - ly * TX;
        int yp = by - 2 + ly, xp = bx - 2 + lx;
        if (IN) {
            S.sp[c][ly][lx] = noise[(((b * NC + c) * HP) + yp) * WP + xp]
                            + img[(((b * NC + c) * NH) + (yp - 1)) * NW + (xp - 1)];
        } else {
            float v = 0.f;
            if (yp >= 0 && yp < HP && xp >= 0 && xp < WP) {
                v = noise[(((b * NC + c) * HP) + yp) * WP + xp];
                if (yp >= 1 && yp <= NH && xp >= 1 && xp <= NW)
                    v += img[(((b * NC + c) * NH) + (yp - 1)) * NW + (xp - 1)];
            }
            S.sp[c][ly][lx] = v;
        }
    }
    __syncthreads();

    // ---- stage A: one img_r item per thread (720 items, 768 threads) ----
    float meanc[NC], ac[NC];            // stats stay in registers for stage B
    const int aly = tid / RX, alx = tid - aly * RX;
    const bool hasA = tid < RY * RX;
    bool inimg = false;
    if (hasA) {
        int hh = by - 2 + aly, ww = bx - 2 + alx;
        inimg = IN || (hh >= 0 && hh < NH && ww >= 0 && ww < NW);
        float rv = 0.f;
        if (inimg) {
            float zmax[9], u[9];
            #pragma unroll
            for (int c = 0; c < NC; c++) {
                float x[9], s = 0.f, ss = 0.f;
                #pragma unroll
                for (int k = 0; k < 9; k++) {
                    x[k] = S.sp[c][aly + k / 3][alx + k % 3];
                    s += x[k];
                    ss = fmaf(x[k], x[k], ss);
                }
                float mn = s * (1.f / 9.f);
                // (0.5/var_ddof1) * log2e = 4*log2e / (ss - s*mean)
                float a  = __fdividef(5.770780163555851f, fmaf(-s, mn, ss));
                meanc[c] = mn;
                ac[c]    = a;
                #pragma unroll
                for (int k = 0; k < 9; k++) {
                    float d = x[k] - mn;
                    float z = d * d * a;
                    if (c == 0) { zmax[k] = z;                 u[k] = x[k]; }
                    else        { zmax[k] = fmaxf(zmax[k], z); u[k] += x[k]; }
                }
            }
            float num = 0.f, den = 0.f;
            #pragma unroll
            for (int k = 0; k < 9; k++) {
                float m = ex2f(-zmax[k]);
                den += m;
                num = fmaf(u[k], m, num);
            }
            rv = __fdividef(num, den);
        }
        S.sr[aly][alx] = rv;
    }
    __syncthreads();

    // ---- stage B: same pixel as this thread's A item (stats in regs) ----
    if (hasA && aly >= 1 && aly <= MY && alx >= 1 && alx <= MX) {
        float mv = 0.f;
        if (inimg) {
            float vmin = S.sr[aly - 1][alx - 1], vmax = vmin;
            int imin = 0, imax = 0;
            #pragma unroll
            for (int k = 1; k < 9; k++) {
                float r = S.sr[aly - 1 + k / 3][alx - 1 + k % 3];
                if (r < vmin) { vmin = r; imin = k; }   // first-occurrence ties
                if (r > vmax) { vmax = r; imax = k; }
            }
            int ids = mix ? imax : imin;
            int ki = ids / 3, kj = ids % 3;
            float zm = 0.f;
            #pragma unroll
            for (int c = 0; c < NC; c++) {
                float d = S.sp[c][aly + ki][alx + kj] - meanc[c];
                zm = fmaxf(zm, d * d * ac[c]);
            }
            mv = ex2f(-zm);
        }
        S.sm[aly - 1][alx - 1] = mv;
    }
    __syncthreads();

    // ---- stage C: final weighted average + blend (512 of 768 threads) ----
    if (ty < BY) {
        const int h = by + ty, w = bx + tx;
        float mk[9], den = 0.f;
        #pragma unroll
        for (int k = 0; k < 9; k++) {
            mk[k] = S.sm[ty + k / 3][tx + k % 3];
            den += mk[k];
        }
        float inv_den = __fdividef(1.f, den);
        #pragma unroll
        for (int c = 0; c < NC; c++) {
            float num = 0.f;
            #pragma unroll
            for (int k = 0; k < 9; k++)
                num = fmaf(S.sp[c][ty + 2 + k / 3][tx + 2 + k % 3], mk[k], num);
            float mod = num * inv_den;
            int gi = (((b * NC + c) * NH) + h) * NW + w;
            float r = re[gi];
            out[gi] = mod * (1.f - r) + img[gi] * r;
        }
    }
}

__global__ __launch_bounds__(NT, 2) void gdfn_fused(
    const float* __restrict__ img, const float* __restrict__ noise,
    const float* __restrict__ re, const int* __restrict__ sel,
    const int* __restrict__ mixsel, float* __restrict__ out)
{
    const int b  = blockIdx.z;
    const int bx = blockIdx.x * BX;
    const int by = blockIdx.y * BY;
    const int tx = threadIdx.x, ty = threadIdx.y;
    const int tid = ty * NTX + tx;

    if (!sel[b]) {  // uniform early-exit: pure copy
        if (ty < BY) {
            int h = by + ty, w = bx + tx;
            #pragma unroll
            for (int c = 0; c < NC; c++) {
                int gi = (((b * NC + c) * NH) + h) * NW + w;
                out[gi] = img[gi];
            }
        }
        return;
    }

    __shared__ Smem S;
    const int mix = mixsel[b];
    // interior <=> every img_p access in [1,512]^2 and every A pixel in-image
    const bool interior = (by >= 3) && (by + TY - 3 <= NH)
                       && (bx >= 3) && (bx + TX - 3 <= NW);
    if (interior) run_tile<true >(S, b, by, bx, tid, tx, ty, mix, img, noise, re, out);
    else          run_tile<false>(S, b, by, bx, tid, tx, ty, mix, img, noise, re, out);
}

extern "C" void kernel_launch(void* const* d_in, const int* in_sizes, int n_in,
                              void* d_out, int out_size)
{
    const float* img    = (const float*)d_in[0];
    const float* noise  = (const float*)d_in[1];
    const float* re     = (const float*)d_in[2];
    const int*   sel    = (const int*)d_in[3];
    const int*   mixsel = (const int*)d_in[4];
    float*       out    = (float*)d_out;

    dim3 blk(NTX, NTY), grd(NW / BX, NH / BY, NB);
    gdfn_fused<<<grd, blk>>>(img, noise, re, sel, mixsel, out);
}

// round 11
// speedup vs baseline: 1.1459x; 1.1459x over previous
#include <cuda_runtime.h>

#define NB 8
#define NC 3
#define NH 512
#define NW 512
#define HP 514
#define WP 514
#define BX 32
#define BY 16
#define NT 512                // 32x16 threads

// shared tile dims
#define TX (BX + 6)           // 38
#define TY (BY + 6)           // 22
#define RX (BX + 4)           // 36
#define RY (BY + 4)           // 20
#define MX (BX + 2)           // 34
#define MY (BY + 2)           // 18

struct Smem {
    float sp[NC][TY][TX];     // img_p tile
    float sr[RY][RX];         // img_r (zero outside image)
    float smean[NC][RY][RX];  // per-channel window mean
    float sa[NC][RY][RX];     // per-channel (0.5/var)*log2e
    float sm[MY][MX];         // img_3d_mod (zero outside image)
};                            // ~32.6 KB

// raw 2^x (MUFU.EX2); exp(-z) == ex2(-z*log2e), log2e folded into 'a'
static __device__ __forceinline__ float ex2f(float x)
{
    float r; asm("ex2.approx.f32 %0, %1;" : "=f"(r) : "f"(x)); return r;
}

// stage A: one img_r pixel + stats
template<bool IN>
static __device__ __forceinline__ void stageA(Smem& S, int i, int by, int bx)
{
    int ly = i / RX, lx = i - ly * RX;
    bool inimg = true;
    if (!IN) {
        int hh = by - 2 + ly, ww = bx - 2 + lx;
        inimg = (hh >= 0 && hh < NH && ww >= 0 && ww < NW);
    }
    float rv = 0.f;
    if (inimg) {
        float zmax[9], u[9];
        #pragma unroll
        for (int c = 0; c < NC; c++) {
            float x[9], s = 0.f, ss = 0.f;
            #pragma unroll
            for (int k = 0; k < 9; k++) {
                x[k] = S.sp[c][ly + k / 3][lx + k % 3];
                s += x[k];
                ss = fmaf(x[k], x[k], ss);
            }
            float mn = s * (1.f / 9.f);
            // (0.5/var_ddof1)*log2e = 4*log2e / (ss - s*mean)
            float a  = __fdividef(5.770780163555854f, fmaf(-s, mn, ss));
            S.smean[c][ly][lx] = mn;
            S.sa[c][ly][lx]    = a;
            #pragma unroll
            for (int k = 0; k < 9; k++) {
                float d = x[k] - mn;
                float z = d * d * a;
                if (c == 0) { zmax[k] = z;                 u[k] = x[k]; }
                else        { zmax[k] = fmaxf(zmax[k], z); u[k] += x[k]; }
            }
        }
        float num = 0.f, den = 0.f;
        #pragma unroll
        for (int k = 0; k < 9; k++) {
            float m = ex2f(-zmax[k]);
            den += m;
            num = fmaf(u[k], m, num);
        }
        rv = __fdividef(num, den);
    }
    S.sr[ly][lx] = rv;
}

// stage B: one mod pixel
template<bool IN>
static __device__ __forceinline__ void stageB(Smem& S, int i, int by, int bx, int mix)
{
    int ly = i / MX, lx = i - ly * MX;
    bool inimg = true;
    if (!IN) {
        int hh = by - 1 + ly, ww = bx - 1 + lx;
        inimg = (hh >= 0 && hh < NH && ww >= 0 && ww < NW);
    }
    float mv = 0.f;
    if (inimg) {
        float vmin = S.sr[ly][lx], vmax = vmin;
        int imin = 0, imax = 0;
        #pragma unroll
        for (int k = 1; k < 9; k++) {
            float r = S.sr[ly + k / 3][lx + k % 3];
            if (r < vmin) { vmin = r; imin = k; }   // first-occurrence ties
            if (r > vmax) { vmax = r; imax = k; }
        }
        int ids = mix ? imax : imin;
        int ki = ids / 3, kj = ids % 3;
        float zm = 0.f;
        #pragma unroll
        for (int c = 0; c < NC; c++) {
            float mn = S.smean[c][ly + 1][lx + 1];
            float a  = S.sa[c][ly + 1][lx + 1];
            float d  = S.sp[c][ly + 1 + ki][lx + 1 + kj] - mn;
            zm = fmaxf(zm, d * d * a);
        }
        mv = ex2f(-zm);
    }
    S.sm[ly][lx] = mv;
}

template<bool IN>
static __device__ __forceinline__ void run_tile(
    Smem& S, int b, int by, int bx, int tid, int mix,
    const float* __restrict__ img, const float* __restrict__ noise,
    const float* __restrict__ re, float* __restrict__ out)
{
    // ---- load img_p tile: sp[c][ly][lx] = img_p[by-2+ly][bx-2+lx] ----
    for (int i = tid; i < NC * TY * TX; i += NT) {
        int c  = i / (TY * TX);
        int rm = i - c * (TY * TX);
        int ly = rm / TX, lx = rm - ly * TX;
        int yp = by - 2 + ly, xp = bx - 2 + lx;
        if (IN) {
            S.sp[c][ly][lx] = noise[(((b * NC + c) * HP) + yp) * WP + xp]
                            + img[(((b * NC + c) * NH) + (yp - 1)) * NW + (xp - 1)];
        } else {
            float v = 0.f;
            if (yp >= 0 && yp < HP && xp >= 0 && xp < WP) {
                v = noise[(((b * NC + c) * HP) + yp) * WP + xp];
                if (yp >= 1 && yp <= NH && xp >= 1 && xp <= NW)
                    v += img[(((b * NC + c) * NH) + (yp - 1)) * NW + (xp - 1)];
            }
            S.sp[c][ly][lx] = v;
        }
    }
    __syncthreads();

    // ---- stage A: 720 items, two passes ----
    stageA<IN>(S, tid, by, bx);
    if (tid + NT < RY * RX) stageA<IN>(S, tid + NT, by, bx);
    __syncthreads();

    // ---- stage B: 612 items, two passes ----
    stageB<IN>(S, tid, by, bx, mix);
    if (tid + NT < MY * MX) stageB<IN>(S, tid + NT, by, bx, mix);
    __syncthreads();

    // ---- stage C: 256 pixel-pairs, float2 I/O (threads 0..255) ----
    if (tid < (BX / 2) * BY) {
        int ty  = tid >> 4;           // 0..15
        int tx2 = (tid & 15) * 2;     // even column 0..30
        // window weights for both pixels: rows ty..ty+2, cols tx2..tx2+3 of sm
        float m[3][4];
        float den0 = 0.f, den1 = 0.f;
        #pragma unroll
        for (int i = 0; i < 3; i++)
            #pragma unroll
            for (int j = 0; j < 4; j++)
                m[i][j] = S.sm[ty + i][tx2 + j];
        #pragma unroll
        for (int i = 0; i < 3; i++) {
            den0 += m[i][0] + m[i][1] + m[i][2];
            den1 += m[i][1] + m[i][2] + m[i][3];
        }
        float id0 = __fdividef(1.f, den0);
        float id1 = __fdividef(1.f, den1);
        const int h = by + ty, w = bx + tx2;
        #pragma unroll
        for (int c = 0; c < NC; c++) {
            float n0 = 0.f, n1 = 0.f;
            #pragma unroll
            for (int i = 0; i < 3; i++) {
                #pragma unroll
                for (int j = 0; j < 4; j++) {
                    // x = sp col tx2+2+j.
                    // pixel0 window cols tx2+2..tx2+4  -> j<3, weight m[i][j]
                    // pixel1 window cols tx2+3..tx2+5  -> j>0, window pos jj=j-1,
                    //        weight sm[ty+i][tx2+1+jj] = m[i][j]
                    float x = S.sp[c][ty + 2 + i][tx2 + 2 + j];
                    if (j < 3) n0 = fmaf(x, m[i][j], n0);
                    if (j > 0) n1 = fmaf(x, m[i][j], n1);
                }
            }
            int gi = (((b * NC + c) * NH) + h) * NW + w;   // even -> 8B aligned
            float2 r2 = *(const float2*)(re + gi);
            float2 i2 = *(const float2*)(img + gi);
            float2 o;
            o.x = n0 * id0 * (1.f - r2.x) + i2.x * r2.x;
            o.y = n1 * id1 * (1.f - r2.y) + i2.y * r2.y;
            *(float2*)(out + gi) = o;
        }
    }
}

__global__ __launch_bounds__(NT, 3) void gdfn_fused(
    const float* __restrict__ img, const float* __restrict__ noise,
    const float* __restrict__ re, const int* __restrict__ sel,
    const int* __restrict__ mixsel, float* __restrict__ out)
{
    const int b  = blockIdx.z;
    const int bx = blockIdx.x * BX;
    const int by = blockIdx.y * BY;
    const int tx = threadIdx.x, ty = threadIdx.y;
    const int tid = ty * BX + tx;

    if (!sel[b]) {  // uniform early-exit: pure copy (no barriers on this path)
        int h = by + ty, w = bx + tx;
        #pragma unroll
        for (int c = 0; c < NC; c++) {
            int gi = (((b * NC + c) * NH) + h) * NW + w;
            out[gi] = img[gi];
        }
        return;
    }

    __shared__ Smem S;
    const int mix = mixsel[b];
    const bool interior = (by >= 3) && (by + TY - 3 <= NH)
                       && (bx >= 3) && (bx + TX - 3 <= NW);
    if (interior) run_tile<true >(S, b, by, bx, tid, mix, img, noise, re, out);
    else          run_tile<false>(S, b, by, bx, tid, mix, img, noise, re, out);
}

extern "C" void kernel_launch(void* const* d_in, const int* in_sizes, int n_in,
                              void* d_out, int out_size)
{
    const float* img    = (const float*)d_in[0];
    const float* noise  = (const float*)d_in[1];
    const float* re     = (const float*)d_in[2];
    const int*   sel    = (const int*)d_in[3];
    const int*   mixsel = (const int*)d_in[4];
    float*       out    = (float*)d_out;

    dim3 blk(BX, BY), grd(NW / BX, NH / BY, NB);
    gdfn_fused<<<grd, blk>>>(img, noise, re, sel, mixsel, out);
}

// round 12
// speedup vs baseline: 1.4171x; 1.2366x over previous
#include <cuda_runtime.h>

#define NB 8
#define NC 3
#define NH 512
#define NW 512
#define HP 514
#define WP 514
#define BX 32
#define BY 16
#define NT 512                // 32x16 threads

// shared tile dims
#define TX (BX + 6)           // 38
#define TY (BY + 6)           // 22
#define RX (BX + 4)           // 36
#define RY (BY + 4)           // 20
#define MX (BX + 2)           // 34
#define MY (BY + 2)           // 18

struct Smem {
    float sp[NC][TY][TX];     // img_p tile
    float usum[TY][TX];       // channel sum of sp
    float sr[RY][RX];         // img_r (zero outside image)
    float smean[NC][RY][RX];  // per-channel window mean
    float sa[NC][RY][RX];     // per-channel (0.5/var)*log2e
    float sm[MY][MX];         // img_3d_mod (zero outside image)
};                            // ~36 KB

// raw 2^x (MUFU.EX2); exp(-z) == ex2(-z*log2e), log2e folded into 'a'
static __device__ __forceinline__ float ex2f(float x)
{
    float r; asm("ex2.approx.f32 %0, %1;" : "=f"(r) : "f"(x)); return r;
}

// stage A: one img_r pixel + stats (u-array removed: num uses usum tile)
template<bool IN>
static __device__ __forceinline__ void stageA(Smem& S, int i, int by, int bx)
{
    int ly = i / RX, lx = i - ly * RX;
    bool inimg = true;
    if (!IN) {
        int hh = by - 2 + ly, ww = bx - 2 + lx;
        inimg = (hh >= 0 && hh < NH && ww >= 0 && ww < NW);
    }
    float rv = 0.f;
    if (inimg) {
        float zmax[9];
        #pragma unroll
        for (int c = 0; c < NC; c++) {
            float x[9], s = 0.f, ss = 0.f;
            #pragma unroll
            for (int k = 0; k < 9; k++) {
                x[k] = S.sp[c][ly + k / 3][lx + k % 3];
                s += x[k];
                ss = fmaf(x[k], x[k], ss);
            }
            float mn = s * (1.f / 9.f);
            // (0.5/var_ddof1)*log2e = 4*log2e / (ss - s*mean)
            float a  = __fdividef(5.770780163555854f, fmaf(-s, mn, ss));
            S.smean[c][ly][lx] = mn;
            S.sa[c][ly][lx]    = a;
            #pragma unroll
            for (int k = 0; k < 9; k++) {
                float d = x[k] - mn;
                float z = d * d * a;
                zmax[k] = (c == 0) ? z : fmaxf(zmax[k], z);
            }
        }
        float num = 0.f, den = 0.f;
        #pragma unroll
        for (int k = 0; k < 9; k++) {
            float m = ex2f(-zmax[k]);
            den += m;
            num = fmaf(S.usum[ly + k / 3][lx + k % 3], m, num);
        }
        rv = __fdividef(num, den);
    }
    S.sr[ly][lx] = rv;
}

// stage B: one mod pixel
template<bool IN>
static __device__ __forceinline__ void stageB(Smem& S, int i, int by, int bx, int mix)
{
    int ly = i / MX, lx = i - ly * MX;
    bool inimg = true;
    if (!IN) {
        int hh = by - 1 + ly, ww = bx - 1 + lx;
        inimg = (hh >= 0 && hh < NH && ww >= 0 && ww < NW);
    }
    float mv = 0.f;
    if (inimg) {
        float vmin = S.sr[ly][lx], vmax = vmin;
        int imin = 0, imax = 0;
        #pragma unroll
        for (int k = 1; k < 9; k++) {
            float r = S.sr[ly + k / 3][lx + k % 3];
            if (r < vmin) { vmin = r; imin = k; }   // first-occurrence ties
            if (r > vmax) { vmax = r; imax = k; }
        }
        int ids = mix ? imax : imin;
        int ki = ids / 3, kj = ids % 3;
        float zm = 0.f;
        #pragma unroll
        for (int c = 0; c < NC; c++) {
            float mn = S.smean[c][ly + 1][lx + 1];
            float a  = S.sa[c][ly + 1][lx + 1];
            float d  = S.sp[c][ly + 1 + ki][lx + 1 + kj] - mn;
            zm = fmaxf(zm, d * d * a);
        }
        mv = ex2f(-zm);
    }
    S.sm[ly][lx] = mv;
}

template<bool IN>
static __device__ __forceinline__ void run_tile(
    Smem& S, int b, int by, int bx, int tid, int mix,
    const float* __restrict__ img, const float* __restrict__ noise,
    const float* __restrict__ re, float* __restrict__ out)
{
    // ---- load img_p tile, pixel-major: all 3 channels + usum per item ----
    for (int i = tid; i < TY * TX; i += NT) {
        int ly = i / TX, lx = i - ly * TX;
        int yp = by - 2 + ly, xp = bx - 2 + lx;
        float v0, v1, v2;
        if (IN) {
            int nbase = ((b * NC) * HP + yp) * WP + xp;
            int ibase = ((b * NC) * NH + (yp - 1)) * NW + (xp - 1);
            v0 = noise[nbase             ] + img[ibase            ];
            v1 = noise[nbase +     HP*WP ] + img[ibase +     NH*NW];
            v2 = noise[nbase + 2 * HP*WP ] + img[ibase + 2 * NH*NW];
        } else {
            v0 = v1 = v2 = 0.f;
            if (yp >= 0 && yp < HP && xp >= 0 && xp < WP) {
                int nbase = ((b * NC) * HP + yp) * WP + xp;
                v0 = noise[nbase];
                v1 = noise[nbase + HP*WP];
                v2 = noise[nbase + 2 * HP*WP];
                if (yp >= 1 && yp <= NH && xp >= 1 && xp <= NW) {
                    int ibase = ((b * NC) * NH + (yp - 1)) * NW + (xp - 1);
                    v0 += img[ibase];
                    v1 += img[ibase + NH*NW];
                    v2 += img[ibase + 2 * NH*NW];
                }
            }
        }
        S.sp[0][ly][lx] = v0;
        S.sp[1][ly][lx] = v1;
        S.sp[2][ly][lx] = v2;
        S.usum[ly][lx]  = v0 + v1 + v2;
    }
    __syncthreads();

    // ---- stage A: 720 items, two passes ----
    stageA<IN>(S, tid, by, bx);
    if (tid + NT < RY * RX) stageA<IN>(S, tid + NT, by, bx);
    __syncthreads();

    // ---- stage B: 612 items, two passes ----
    stageB<IN>(S, tid, by, bx, mix);
    if (tid + NT < MY * MX) stageB<IN>(S, tid + NT, by, bx, mix);
    __syncthreads();

    // ---- stage C: 256 pixel-pairs, float2 I/O (threads 0..255) ----
    if (tid < (BX / 2) * BY) {
        int ty  = tid >> 4;           // 0..15
        int tx2 = (tid & 15) * 2;     // even column 0..30
        float m[3][4];
        float den0 = 0.f, den1 = 0.f;
        #pragma unroll
        for (int i = 0; i < 3; i++)
            #pragma unroll
            for (int j = 0; j < 4; j++)
                m[i][j] = S.sm[ty + i][tx2 + j];
        #pragma unroll
        for (int i = 0; i < 3; i++) {
            den0 += m[i][0] + m[i][1] + m[i][2];
            den1 += m[i][1] + m[i][2] + m[i][3];
        }
        float id0 = __fdividef(1.f, den0);
        float id1 = __fdividef(1.f, den1);
        const int h = by + ty, w = bx + tx2;
        #pragma unroll
        for (int c = 0; c < NC; c++) {
            float n0 = 0.f, n1 = 0.f;
            #pragma unroll
            for (int i = 0; i < 3; i++) {
                #pragma unroll
                for (int j = 0; j < 4; j++) {
                    // pixel0 weight m[i][j] (j<3); pixel1 weight m[i][j] (j>0)
                    float x = S.sp[c][ty + 2 + i][tx2 + 2 + j];
                    if (j < 3) n0 = fmaf(x, m[i][j], n0);
                    if (j > 0) n1 = fmaf(x, m[i][j], n1);
                }
            }
            int gi = (((b * NC + c) * NH) + h) * NW + w;   // even -> 8B aligned
            float2 r2 = *(const float2*)(re + gi);
            float2 i2 = *(const float2*)(img + gi);
            float2 o;
            o.x = n0 * id0 * (1.f - r2.x) + i2.x * r2.x;
            o.y = n1 * id1 * (1.f - r2.y) + i2.y * r2.y;
            *(float2*)(out + gi) = o;
        }
    }
}

__global__ __launch_bounds__(NT, 4) void gdfn_fused(
    const float* __restrict__ img, const float* __restrict__ noise,
    const float* __restrict__ re, const int* __restrict__ sel,
    const int* __restrict__ mixsel, float* __restrict__ out)
{
    const int b  = blockIdx.z;
    const int bx = blockIdx.x * BX;
    const int by = blockIdx.y * BY;
    const int tx = threadIdx.x, ty = threadIdx.y;
    const int tid = ty * BX + tx;

    if (!sel[b]) {  // uniform early-exit: pure copy (no barriers on this path)
        int h = by + ty, w = bx + tx;
        #pragma unroll
        for (int c = 0; c < NC; c++) {
            int gi = (((b * NC + c) * NH) + h) * NW + w;
            out[gi] = img[gi];
        }
        return;
    }

    __shared__ Smem S;
    const int mix = mixsel[b];
    const bool interior = (by >= 3) && (by + TY - 3 <= NH)
                       && (bx >= 3) && (bx + TX - 3 <= NW);
    if (interior) run_tile<true >(S, b, by, bx, tid, mix, img, noise, re, out);
    else          run_tile<false>(S, b, by, bx, tid, mix, img, noise, re, out);
}

extern "C" void kernel_launch(void* const* d_in, const int* in_sizes, int n_in,
                              void* d_out, int out_size)
{
    const float* img    = (const float*)d_in[0];
    const float* noise  = (const float*)d_in[1];
    const float* re     = (const float*)d_in[2];
    const int*   sel    = (const int*)d_in[3];
    const int*   mixsel = (const int*)d_in[4];
    float*       out    = (float*)d_out;

    dim3 blk(BX, BY), grd(NW / BX, NH / BY, NB);
    gdfn_fused<<<grd, blk>>>(img, noise, re, sel, mixsel, out);
}

// round 13
// speedup vs baseline: 1.4878x; 1.0499x over previous
#include <cuda_runtime.h>

#define NB 8
#define NC 3
#define NH 512
#define NW 512
#define HP 514
#define WP 514
#define BX 32
#define BY 16
#define NT 512                // 32x16 threads

// shared tile dims
#define TX (BX + 6)           // 38
#define TY (BY + 6)           // 22
#define RX (BX + 4)           // 36
#define RY (BY + 4)           // 20
#define MX (BX + 2)           // 34
#define MY (BY + 2)           // 18

struct Smem {
    float  sp[NC][TY][TX];     // img_p tile
    float  usum[TY][TX];       // channel sum of sp
    float  sr[RY][RX];         // img_r (zero outside image)
    float2 sstat[NC][RY][RX];  // (mean, (0.5/var)*log2e) per channel
    float  sm[MY][MX];         // img_3d_mod (zero outside image)
};                             // ~35.1 KB (< 48 KB static limit)

// raw 2^x (MUFU.EX2); exp(-z) == ex2(-z*log2e), log2e folded into 'a'
static __device__ __forceinline__ float ex2f(float x)
{
    float r; asm("ex2.approx.f32 %0, %1;" : "=f"(r) : "f"(x)); return r;
}

// stage A: one img_r pixel + stats (num uses usum tile; stats stored as float2)
template<bool IN>
static __device__ __forceinline__ void stageA(Smem& S, int i, int by, int bx)
{
    int ly = i / RX, lx = i - ly * RX;
    bool inimg = true;
    if (!IN) {
        int hh = by - 2 + ly, ww = bx - 2 + lx;
        inimg = (hh >= 0 && hh < NH && ww >= 0 && ww < NW);
    }
    float rv = 0.f;
    if (inimg) {
        float zmax[9];
        #pragma unroll
        for (int c = 0; c < NC; c++) {
            float x[9], s = 0.f, ss = 0.f;
            #pragma unroll
            for (int k = 0; k < 9; k++) {
                x[k] = S.sp[c][ly + k / 3][lx + k % 3];
                s += x[k];
                ss = fmaf(x[k], x[k], ss);
            }
            float mn = s * (1.f / 9.f);
            // (0.5/var_ddof1)*log2e = 4*log2e / (ss - s*mean)
            float a  = __fdividef(5.770780163555854f, fmaf(-s, mn, ss));
            S.sstat[c][ly][lx] = make_float2(mn, a);
            #pragma unroll
            for (int k = 0; k < 9; k++) {
                float d = x[k] - mn;
                float z = d * d * a;
                zmax[k] = (c == 0) ? z : fmaxf(zmax[k], z);
            }
        }
        float num = 0.f, den = 0.f;
        #pragma unroll
        for (int k = 0; k < 9; k++) {
            float m = ex2f(-zmax[k]);
            den += m;
            num = fmaf(S.usum[ly + k / 3][lx + k % 3], m, num);
        }
        rv = __fdividef(num, den);
    }
    S.sr[ly][lx] = rv;
}

// stage B: one mod pixel (stats read as float2)
template<bool IN>
static __device__ __forceinline__ void stageB(Smem& S, int i, int by, int bx, int mix)
{
    int ly = i / MX, lx = i - ly * MX;
    bool inimg = true;
    if (!IN) {
        int hh = by - 1 + ly, ww = bx - 1 + lx;
        inimg = (hh >= 0 && hh < NH && ww >= 0 && ww < NW);
    }
    float mv = 0.f;
    if (inimg) {
        float vmin = S.sr[ly][lx], vmax = vmin;
        int imin = 0, imax = 0;
        #pragma unroll
        for (int k = 1; k < 9; k++) {
            float r = S.sr[ly + k / 3][lx + k % 3];
            if (r < vmin) { vmin = r; imin = k; }   // first-occurrence ties
            if (r > vmax) { vmax = r; imax = k; }
        }
        int ids = mix ? imax : imin;
        int ki = ids / 3, kj = ids % 3;
        float zm = 0.f;
        #pragma unroll
        for (int c = 0; c < NC; c++) {
            float2 st = S.sstat[c][ly + 1][lx + 1];
            float d  = S.sp[c][ly + 1 + ki][lx + 1 + kj] - st.x;
            zm = fmaxf(zm, d * d * st.y);
        }
        mv = ex2f(-zm);
    }
    S.sm[ly][lx] = mv;
}

template<bool IN>
static __device__ __forceinline__ void run_tile(
    Smem& S, int b, int by, int bx, int tid, int mix,
    const float* __restrict__ img, const float* __restrict__ noise,
    const float* __restrict__ re, float* __restrict__ out)
{
    // ---- load img_p tile, pixel-major: all 3 channels + usum per item ----
    for (int i = tid; i < TY * TX; i += NT) {
        int ly = i / TX, lx = i - ly * TX;
        int yp = by - 2 + ly, xp = bx - 2 + lx;
        float v0, v1, v2;
        if (IN) {
            int nbase = ((b * NC) * HP + yp) * WP + xp;
            int ibase = ((b * NC) * NH + (yp - 1)) * NW + (xp - 1);
            v0 = noise[nbase             ] + img[ibase            ];
            v1 = noise[nbase +     HP*WP ] + img[ibase +     NH*NW];
            v2 = noise[nbase + 2 * HP*WP ] + img[ibase + 2 * NH*NW];
        } else {
            v0 = v1 = v2 = 0.f;
            if (yp >= 0 && yp < HP && xp >= 0 && xp < WP) {
                int nbase = ((b * NC) * HP + yp) * WP + xp;
                v0 = noise[nbase];
                v1 = noise[nbase + HP*WP];
                v2 = noise[nbase + 2 * HP*WP];
                if (yp >= 1 && yp <= NH && xp >= 1 && xp <= NW) {
                    int ibase = ((b * NC) * NH + (yp - 1)) * NW + (xp - 1);
                    v0 += img[ibase];
                    v1 += img[ibase + NH*NW];
                    v2 += img[ibase + 2 * NH*NW];
                }
            }
        }
        S.sp[0][ly][lx] = v0;
        S.sp[1][ly][lx] = v1;
        S.sp[2][ly][lx] = v2;
        S.usum[ly][lx]  = v0 + v1 + v2;
    }
    __syncthreads();

    // ---- stage A: 720 items, two passes ----
    stageA<IN>(S, tid, by, bx);
    if (tid + NT < RY * RX) stageA<IN>(S, tid + NT, by, bx);
    __syncthreads();

    // ---- stage B: 612 items, two passes ----
    stageB<IN>(S, tid, by, bx, mix);
    if (tid + NT < MY * MX) stageB<IN>(S, tid + NT, by, bx, mix);
    __syncthreads();

    // ---- stage C: 256 pixel-pairs, float2 smem + gmem I/O (threads 0..255) ----
    if (tid < (BX / 2) * BY) {
        int ty  = tid >> 4;           // 0..15
        int tx2 = (tid & 15) * 2;     // even column 0..30
        // weights: sm rows ty..ty+2, cols tx2..tx2+3 as two float2 per row
        float2 ma[3], mb[3];
        #pragma unroll
        for (int i = 0; i < 3; i++) {
            ma[i] = *(const float2*)&S.sm[ty + i][tx2];      // m[i][0], m[i][1]
            mb[i] = *(const float2*)&S.sm[ty + i][tx2 + 2];  // m[i][2], m[i][3]
        }
        float den0 = 0.f, den1 = 0.f;
        #pragma unroll
        for (int i = 0; i < 3; i++) {
            den0 += ma[i].x + ma[i].y + mb[i].x;
            den1 += ma[i].y + mb[i].x + mb[i].y;
        }
        float id0 = __fdividef(1.f, den0);
        float id1 = __fdividef(1.f, den1);
        const int h = by + ty, w = bx + tx2;
        #pragma unroll
        for (int c = 0; c < NC; c++) {
            float n0 = 0.f, n1 = 0.f;
            #pragma unroll
            for (int i = 0; i < 3; i++) {
                // sp cols tx2+2 .. tx2+5 as two float2
                float2 p = *(const float2*)&S.sp[c][ty + 2 + i][tx2 + 2];
                float2 q = *(const float2*)&S.sp[c][ty + 2 + i][tx2 + 4];
                // pixel0: p.x*m0 + p.y*m1 + q.x*m2 ; pixel1: p.y*m1 + q.x*m2 + q.y*m3
                float t1 = p.y * ma[i].y;
                float t2 = q.x * mb[i].x;
                n0 += fmaf(p.x, ma[i].x, t1 + t2);
                n1 += fmaf(q.y, mb[i].y, t1 + t2);
            }
            int gi = (((b * NC + c) * NH) + h) * NW + w;   // even -> 8B aligned
            float2 r2 = *(const float2*)(re + gi);
            float2 i2 = *(const float2*)(img + gi);
            float2 o;
            o.x = n0 * id0 * (1.f - r2.x) + i2.x * r2.x;
            o.y = n1 * id1 * (1.f - r2.y) + i2.y * r2.y;
            *(float2*)(out + gi) = o;
        }
    }
}

__global__ __launch_bounds__(NT, 4) void gdfn_fused(
    const float* __restrict__ img, const float* __restrict__ noise,
    const float* __restrict__ re, const int* __restrict__ sel,
    const int* __restrict__ mixsel, float* __restrict__ out)
{
    const int b  = blockIdx.z;
    const int bx = blockIdx.x * BX;
    const int by = blockIdx.y * BY;
    const int tx = threadIdx.x, ty = threadIdx.y;
    const int tid = ty * BX + tx;

    if (!sel[b]) {  // uniform early-exit: pure copy (no barriers on this path)
        int h = by + ty, w = bx + tx;
        #pragma unroll
        for (int c = 0; c < NC; c++) {
            int gi = (((b * NC + c) * NH) + h) * NW + w;
            out[gi] = img[gi];
        }
        return;
    }

    __shared__ Smem S;
    const int mix = mixsel[b];
    const bool interior = (by >= 3) && (by + TY - 3 <= NH)
                       && (bx >= 3) && (bx + TX - 3 <= NW);
    if (interior) run_tile<true >(S, b, by, bx, tid, mix, img, noise, re, out);
    else          run_tile<false>(S, b, by, bx, tid, mix, img, noise, re, out);
}

extern "C" void kernel_launch(void* const* d_in, const int* in_sizes, int n_in,
                              void* d_out, int out_size)
{
    const float* img    = (const float*)d_in[0];
    const float* noise  = (const float*)d_in[1];
    const float* re     = (const float*)d_in[2];
    const int*   sel    = (const int*)d_in[3];
    const int*   mixsel = (const int*)d_in[4];
    float*       out    = (float*)d_out;

    dim3 blk(BX, BY), grd(NW / BX, NH / BY, NB);
    gdfn_fused<<<grd, blk>>>(img, noise, re, sel, mixsel, out);
}